// round 1
// baseline (speedup 1.0000x reference)
#include <cuda_runtime.h>
#include <math.h>

// Causal self-attention, B=4, S=2048, D=1024, fp32.
// Round 0: structurally-sound fp32 SIMT implementation.
//   k1: QKV = X @ W^T        (fused NT-GEMM, z selects W_Q/W_K/W_V)
//   k2: S = (Q @ K^T)/32     (NT-GEMM, fully-masked 128x128 tiles skipped)
//   k3: row softmax in-place (writes exact zeros above the diagonal)
//   k4: O = P @ V            (NN-GEMM, k-loop limited to causal frontier)

#define B_   4
#define S_   2048
#define D_   1024
#define BM   128
#define BN   128
#define BK   16
#define LDS_ (BM + 4)   // 132: keeps 16B alignment for LDS.128, breaks store conflicts

// Scratch (allocation-free rule: __device__ globals)
__device__ float g_Q[(size_t)B_ * S_ * D_];
__device__ float g_K[(size_t)B_ * S_ * D_];
__device__ float g_V[(size_t)B_ * S_ * D_];
__device__ float g_S[(size_t)B_ * S_ * S_];

// ---------------------------------------------------------------------------
// C[M,N] += A[M,K] * B[N,K]^T   (both K-contiguous). 128x128 tile, 256 thr,
// 8x8 micro-tile per thread in 2x2 float4 groups -> conflict-free LDS.128.
// ---------------------------------------------------------------------------
__device__ __forceinline__ void gemm_nt_core(
    const float* __restrict__ A, const float* __restrict__ Bg, float* __restrict__ C,
    int lda, int ldc, float alpha, int m0, int n0, int ktiles)
{
    __shared__ float As[BK][LDS_];
    __shared__ float Bs[BK][LDS_];
    const int tid = threadIdx.x;
    const int tx  = tid & 15;
    const int ty  = tid >> 4;
    const int lr  = tid >> 2;        // 0..63
    const int lk  = (tid & 3) * 4;   // 0,4,8,12

    float acc[8][8];
#pragma unroll
    for (int i = 0; i < 8; i++)
#pragma unroll
        for (int j = 0; j < 8; j++) acc[i][j] = 0.f;

    for (int kt = 0; kt < ktiles; ++kt) {
        const int k0 = kt * BK;
#pragma unroll
        for (int it = 0; it < 2; ++it) {
            const int r = lr + it * 64;
            const float4 v = *reinterpret_cast<const float4*>(
                &A[(size_t)(m0 + r) * lda + k0 + lk]);
            As[lk + 0][r] = v.x; As[lk + 1][r] = v.y;
            As[lk + 2][r] = v.z; As[lk + 3][r] = v.w;
        }
#pragma unroll
        for (int it = 0; it < 2; ++it) {
            const int r = lr + it * 64;
            const float4 v = *reinterpret_cast<const float4*>(
                &Bg[(size_t)(n0 + r) * lda + k0 + lk]);
            Bs[lk + 0][r] = v.x; Bs[lk + 1][r] = v.y;
            Bs[lk + 2][r] = v.z; Bs[lk + 3][r] = v.w;
        }
        __syncthreads();
#pragma unroll
        for (int k = 0; k < BK; k++) {
            const float4 a0 = *reinterpret_cast<const float4*>(&As[k][ty * 4]);
            const float4 a1 = *reinterpret_cast<const float4*>(&As[k][64 + ty * 4]);
            const float4 b0 = *reinterpret_cast<const float4*>(&Bs[k][tx * 4]);
            const float4 b1 = *reinterpret_cast<const float4*>(&Bs[k][64 + tx * 4]);
            const float ra[8] = {a0.x, a0.y, a0.z, a0.w, a1.x, a1.y, a1.z, a1.w};
            const float rb[8] = {b0.x, b0.y, b0.z, b0.w, b1.x, b1.y, b1.z, b1.w};
#pragma unroll
            for (int i = 0; i < 8; i++)
#pragma unroll
                for (int j = 0; j < 8; j++)
                    acc[i][j] = fmaf(ra[i], rb[j], acc[i][j]);
        }
        __syncthreads();
    }
#pragma unroll
    for (int i = 0; i < 8; i++) {
        const int r = m0 + ((i < 4) ? ty * 4 + i : 64 + ty * 4 + i - 4);
#pragma unroll
        for (int jg = 0; jg < 2; ++jg) {
            const int c = n0 + jg * 64 + tx * 4;
            float4 v;
            v.x = acc[i][jg * 4 + 0] * alpha;
            v.y = acc[i][jg * 4 + 1] * alpha;
            v.z = acc[i][jg * 4 + 2] * alpha;
            v.w = acc[i][jg * 4 + 3] * alpha;
            *reinterpret_cast<float4*>(&C[(size_t)r * ldc + c]) = v;
        }
    }
}

// ---------------------------------------------------------------------------
// C[M,N] += A[M,K] * B[K,N]   (B N-contiguous).
// ---------------------------------------------------------------------------
__device__ __forceinline__ void gemm_nn_core(
    const float* __restrict__ A, const float* __restrict__ Bg, float* __restrict__ C,
    int lda, int ldb, int ldc, float alpha, int m0, int n0, int ktiles)
{
    __shared__ float As[BK][LDS_];
    __shared__ float Bs[BK][LDS_];
    const int tid = threadIdx.x;
    const int tx  = tid & 15;
    const int ty  = tid >> 4;
    const int lr  = tid >> 2;
    const int lk  = (tid & 3) * 4;
    const int bkk = tid >> 5;        // 0..7
    const int bn  = (tid & 31) * 4;  // 0..124

    float acc[8][8];
#pragma unroll
    for (int i = 0; i < 8; i++)
#pragma unroll
        for (int j = 0; j < 8; j++) acc[i][j] = 0.f;

    for (int kt = 0; kt < ktiles; ++kt) {
        const int k0 = kt * BK;
#pragma unroll
        for (int it = 0; it < 2; ++it) {
            const int r = lr + it * 64;
            const float4 v = *reinterpret_cast<const float4*>(
                &A[(size_t)(m0 + r) * lda + k0 + lk]);
            As[lk + 0][r] = v.x; As[lk + 1][r] = v.y;
            As[lk + 2][r] = v.z; As[lk + 3][r] = v.w;
        }
#pragma unroll
        for (int it = 0; it < 2; ++it) {
            const int kk = bkk + it * 8;
            const float4 v = *reinterpret_cast<const float4*>(
                &Bg[(size_t)(k0 + kk) * ldb + n0 + bn]);
            *reinterpret_cast<float4*>(&Bs[kk][bn]) = v;
        }
        __syncthreads();
#pragma unroll
        for (int k = 0; k < BK; k++) {
            const float4 a0 = *reinterpret_cast<const float4*>(&As[k][ty * 4]);
            const float4 a1 = *reinterpret_cast<const float4*>(&As[k][64 + ty * 4]);
            const float4 b0 = *reinterpret_cast<const float4*>(&Bs[k][tx * 4]);
            const float4 b1 = *reinterpret_cast<const float4*>(&Bs[k][64 + tx * 4]);
            const float ra[8] = {a0.x, a0.y, a0.z, a0.w, a1.x, a1.y, a1.z, a1.w};
            const float rb[8] = {b0.x, b0.y, b0.z, b0.w, b1.x, b1.y, b1.z, b1.w};
#pragma unroll
            for (int i = 0; i < 8; i++)
#pragma unroll
                for (int j = 0; j < 8; j++)
                    acc[i][j] = fmaf(ra[i], rb[j], acc[i][j]);
        }
        __syncthreads();
    }
#pragma unroll
    for (int i = 0; i < 8; i++) {
        const int r = m0 + ((i < 4) ? ty * 4 + i : 64 + ty * 4 + i - 4);
#pragma unroll
        for (int jg = 0; jg < 2; ++jg) {
            const int c = n0 + jg * 64 + tx * 4;
            float4 v;
            v.x = acc[i][jg * 4 + 0] * alpha;
            v.y = acc[i][jg * 4 + 1] * alpha;
            v.z = acc[i][jg * 4 + 2] * alpha;
            v.w = acc[i][jg * 4 + 3] * alpha;
            *reinterpret_cast<float4*>(&C[(size_t)r * ldc + c]) = v;
        }
    }
}

// ---------------------------------------------------------------------------
// Kernels
// ---------------------------------------------------------------------------
__global__ void __launch_bounds__(256) qkv_kernel(
    const float* __restrict__ X, const float* __restrict__ WQ,
    const float* __restrict__ WK, const float* __restrict__ WV)
{
    const float* W = (blockIdx.z == 0) ? WQ : ((blockIdx.z == 1) ? WK : WV);
    float*       O = (blockIdx.z == 0) ? g_Q : ((blockIdx.z == 1) ? g_K : g_V);
    gemm_nt_core(X, W, O, D_, D_, 1.0f,
                 blockIdx.y * BM, blockIdx.x * BN, D_ / BK);
}

__global__ void __launch_bounds__(256) scores_kernel()
{
    if (blockIdx.x > blockIdx.y) return;  // tile fully above diagonal: never read
    const int b = blockIdx.z;
    const float* Q  = g_Q + (size_t)b * S_ * D_;
    const float* Kp = g_K + (size_t)b * S_ * D_;
    float*       Sc = g_S + (size_t)b * S_ * S_;
    gemm_nt_core(Q, Kp, Sc, D_, S_, 0.03125f /* 1/sqrt(1024) */,
                 blockIdx.y * BM, blockIdx.x * BN, D_ / BK);
}

__global__ void __launch_bounds__(256) softmax_kernel()
{
    const int q = blockIdx.x, b = blockIdx.y;
    float* row = g_S + ((size_t)b * S_ + q) * S_;
    const int L = q + 1;
    const int tid = threadIdx.x;
    __shared__ float red[256];

    float m = -3.4e38f;
    for (int j = tid; j < L; j += 256) m = fmaxf(m, row[j]);
    red[tid] = m; __syncthreads();
    for (int s = 128; s > 0; s >>= 1) {
        if (tid < s) red[tid] = fmaxf(red[tid], red[tid + s]);
        __syncthreads();
    }
    m = red[0]; __syncthreads();

    float s = 0.f;
    for (int j = tid; j < L; j += 256) {
        const float e = expf(row[j] - m);
        row[j] = e;
        s += e;
    }
    red[tid] = s; __syncthreads();
    for (int st = 128; st > 0; st >>= 1) {
        if (tid < st) red[tid] += red[tid + st];
        __syncthreads();
    }
    const float inv = 1.f / red[0];
    for (int j = tid; j < L; j += 256) row[j] *= inv;
    for (int j = L + tid; j < S_; j += 256) row[j] = 0.f;  // exact zeros above diag
}

__global__ void __launch_bounds__(256) pv_kernel(float* __restrict__ Out)
{
    const int b  = blockIdx.z;
    const int m0 = blockIdx.y * BM;
    const float* P = g_S + (size_t)b * S_ * S_;
    const float* V = g_V + (size_t)b * S_ * D_;
    float*       O = Out + (size_t)b * S_ * D_;
    const int ktiles = (m0 + BM) / BK;  // causal: P[q, j]=0 for j > q
    gemm_nn_core(P, V, O, S_, D_, D_, 1.0f, m0, blockIdx.x * BN, ktiles);
}

// ---------------------------------------------------------------------------
extern "C" void kernel_launch(void* const* d_in, const int* in_sizes, int n_in,
                              void* d_out, int out_size)
{
    (void)in_sizes; (void)n_in; (void)out_size;
    const float* X  = (const float*)d_in[0];
    const float* WQ = (const float*)d_in[1];
    const float* WK = (const float*)d_in[2];
    const float* WV = (const float*)d_in[3];
    float* out = (float*)d_out;

    qkv_kernel   <<<dim3(D_ / BN, (B_ * S_) / BM, 3), 256>>>(X, WQ, WK, WV);
    scores_kernel<<<dim3(S_ / BN, S_ / BM, B_), 256>>>();
    softmax_kernel<<<dim3(S_, B_), 256>>>();
    pv_kernel    <<<dim3(D_ / BN, S_ / BM, B_), 256>>>(out);
}

// round 3
// speedup vs baseline: 1.9073x; 1.9073x over previous
#include <cuda_runtime.h>
#include <cuda_bf16.h>
#include <cstdint>
#include <math.h>

// Causal self-attention B=4,S=2048,D=1024 fp32.
// Tensor-core path via baseline-PTX mma.sync (HMMA) — tcgen05 is unavailable
// because the harness emits compute_103 (non-'a') PTX.
// Numerics: split fp32 -> hi+lo bf16; GEMM = Ahi*Bhi + Ahi*Blo + Alo*Bhi (fp32 acc).

#define B_  4
#define S_  2048
#define D_  1024
#define TM  128
#define TN  64
#define BK  32

// smem tiles with padded strides (bytes): A 128x32 @ stride 80B, B 64x32 @ 80B (NT)
// or 32x64 @ 144B (NN). All ldmatrix-conflict-free.
#define A_STRIDE_B 80
#define B_NT_STRIDE_B 80
#define B_NN_STRIDE_B 144
#define SM_AH 0
#define SM_AL (128 * A_STRIDE_B)                  // 10240
#define SM_BH (2 * 128 * A_STRIDE_B)              // 20480
#define SM_BL (2 * 128 * A_STRIDE_B + 5760)       // 26240 (max(64*80,32*144)=5760? 64*80=5120,32*144=4608 -> 5760 safe)
#define SM_TOTAL (2 * 128 * A_STRIDE_B + 2 * 5760)

// ---------------- scratch --------------------------------------------------
__device__ alignas(256) __nv_bfloat16 g_Xhi[(size_t)B_*S_*D_], g_Xlo[(size_t)B_*S_*D_];
__device__ alignas(256) __nv_bfloat16 g_Whi[3][(size_t)D_*D_], g_Wlo[3][(size_t)D_*D_];
__device__ alignas(256) __nv_bfloat16 g_Qhi[(size_t)B_*S_*D_], g_Qlo[(size_t)B_*S_*D_];
__device__ alignas(256) __nv_bfloat16 g_Khi[(size_t)B_*S_*D_], g_Klo[(size_t)B_*S_*D_];
__device__ alignas(256) __nv_bfloat16 g_Vhi[(size_t)B_*S_*D_], g_Vlo[(size_t)B_*S_*D_];
__device__ alignas(256) float         g_S[(size_t)B_*S_*S_];
__device__ alignas(256) __nv_bfloat16 g_Phi[(size_t)B_*S_*S_], g_Plo[(size_t)B_*S_*S_];

// ---------------- PTX helpers ----------------------------------------------
__device__ __forceinline__ uint32_t smem_u32(const void* p) {
    uint32_t a;
    asm("{ .reg .u64 t; cvta.to.shared.u64 t, %1; cvt.u32.u64 %0, t; }" : "=r"(a) : "l"(p));
    return a;
}
__device__ __forceinline__ void ldm_x4(uint32_t* r, uint32_t addr) {
    asm volatile("ldmatrix.sync.aligned.m8n8.x4.shared.b16 {%0,%1,%2,%3}, [%4];"
                 : "=r"(r[0]), "=r"(r[1]), "=r"(r[2]), "=r"(r[3]) : "r"(addr));
}
__device__ __forceinline__ void ldm_x2(uint32_t* r, uint32_t addr) {
    asm volatile("ldmatrix.sync.aligned.m8n8.x2.shared.b16 {%0,%1}, [%2];"
                 : "=r"(r[0]), "=r"(r[1]) : "r"(addr));
}
__device__ __forceinline__ void ldm_x2_t(uint32_t* r, uint32_t addr) {
    asm volatile("ldmatrix.sync.aligned.m8n8.x2.trans.shared.b16 {%0,%1}, [%2];"
                 : "=r"(r[0]), "=r"(r[1]) : "r"(addr));
}
__device__ __forceinline__ void mma_bf16(float* d, const uint32_t* a, const uint32_t* b) {
    asm volatile("mma.sync.aligned.m16n8k16.row.col.f32.bf16.bf16.f32 "
                 "{%0,%1,%2,%3}, {%4,%5,%6,%7}, {%8,%9}, {%0,%1,%2,%3};"
                 : "+f"(d[0]), "+f"(d[1]), "+f"(d[2]), "+f"(d[3])
                 : "r"(a[0]), "r"(a[1]), "r"(a[2]), "r"(a[3]), "r"(b[0]), "r"(b[1]));
}

// ---------------- staging ---------------------------------------------------
// A tile: 128 rows x 32 bf16 (64B), 512 float4 -> 256 thr x 2
__device__ __forceinline__ void stage_A(char* dst, const __nv_bfloat16* src, int ld, int k0) {
    const int tid = threadIdx.x;
#pragma unroll
    for (int i = 0; i < 2; ++i) {
        const int s = tid + i * 256;
        const int row = s >> 2, seg = s & 3;
        const float4 v = *reinterpret_cast<const float4*>(src + (size_t)row * ld + k0 + seg * 8);
        *reinterpret_cast<float4*>(dst + row * A_STRIDE_B + seg * 16) = v;
    }
}
// B NT tile: 64 rows x 32 bf16 -> 256 float4
__device__ __forceinline__ void stage_B_nt(char* dst, const __nv_bfloat16* src, int ld, int k0) {
    const int s = threadIdx.x;
    const int row = s >> 2, seg = s & 3;
    const float4 v = *reinterpret_cast<const float4*>(src + (size_t)row * ld + k0 + seg * 8);
    *reinterpret_cast<float4*>(dst + row * B_NT_STRIDE_B + seg * 16) = v;
}
// B NN tile: 32 rows (k) x 64 bf16 (n) -> 256 float4
__device__ __forceinline__ void stage_B_nn(char* dst, const __nv_bfloat16* src, int ld, int k0) {
    const int s = threadIdx.x;
    const int row = s >> 3, seg = s & 7;
    const float4 v = *reinterpret_cast<const float4*>(src + (size_t)(k0 + row) * ld + seg * 8);
    *reinterpret_cast<float4*>(dst + row * B_NN_STRIDE_B + seg * 16) = v;
}

// ---------------- 3-term mainloop ------------------------------------------
// acc[tm][tn][4]; A: [M=128,K] K-contig (hi/lo); B NT: [N=64,K]; B NN: [K,N=64] (pass base+n0)
__device__ __forceinline__ void mma_mainloop(
    char* sm, const __nv_bfloat16* Ah, const __nv_bfloat16* Al,
    const __nv_bfloat16* Bh, const __nv_bfloat16* Bl,
    int lda, int ldb, int nchunks, bool nnB, float acc[2][4][4])
{
    const uint32_t sb = smem_u32(sm);
    const int tid = threadIdx.x;
    const int lane = tid & 31, w = tid >> 5;
    const int wm = w & 3, wn = w >> 2;

    // ldmatrix lane addressing (byte offsets within tiles)
    const uint32_t a_off = (uint32_t)(wm * 32 + (lane & 15)) * A_STRIDE_B + ((lane >> 4) << 3) * 2;
    const uint32_t bnt_off = (uint32_t)(wn * 32 + (lane & 7)) * B_NT_STRIDE_B + ((lane >> 3) & 1) * 16;
    const uint32_t bnn_off = (uint32_t)(lane & 15) * B_NN_STRIDE_B + (uint32_t)(wn * 32) * 2;

    for (int c = 0; c < nchunks; ++c) {
        const int k0 = c * BK;
        stage_A(sm + SM_AH, Ah, lda, k0);
        stage_A(sm + SM_AL, Al, lda, k0);
        if (nnB) { stage_B_nn(sm + SM_BH, Bh, ldb, k0); stage_B_nn(sm + SM_BL, Bl, ldb, k0); }
        else     { stage_B_nt(sm + SM_BH, Bh, ldb, k0); stage_B_nt(sm + SM_BL, Bl, ldb, k0); }
        __syncthreads();
#pragma unroll
        for (int ks = 0; ks < 2; ++ks) {
            const uint32_t kb = ks * 32;   // 16 elems * 2B
            uint32_t ah[2][4], al[2][4], bh[4][2], bl[4][2];
#pragma unroll
            for (int tm = 0; tm < 2; ++tm) {
                ldm_x4(ah[tm], sb + SM_AH + a_off + tm * (16 * A_STRIDE_B) + kb);
                ldm_x4(al[tm], sb + SM_AL + a_off + tm * (16 * A_STRIDE_B) + kb);
            }
            if (nnB) {
#pragma unroll
                for (int tn = 0; tn < 4; ++tn) {
                    ldm_x2_t(bh[tn], sb + SM_BH + bnn_off + kb * (B_NN_STRIDE_B / 2) + tn * 16);
                    ldm_x2_t(bl[tn], sb + SM_BL + bnn_off + kb * (B_NN_STRIDE_B / 2) + tn * 16);
                }
            } else {
#pragma unroll
                for (int tn = 0; tn < 4; ++tn) {
                    ldm_x2(bh[tn], sb + SM_BH + bnt_off + tn * (8 * B_NT_STRIDE_B) + kb);
                    ldm_x2(bl[tn], sb + SM_BL + bnt_off + tn * (8 * B_NT_STRIDE_B) + kb);
                }
            }
#pragma unroll
            for (int tm = 0; tm < 2; ++tm)
#pragma unroll
                for (int tn = 0; tn < 4; ++tn) {
                    mma_bf16(acc[tm][tn], ah[tm], bh[tn]);
                    mma_bf16(acc[tm][tn], ah[tm], bl[tn]);
                    mma_bf16(acc[tm][tn], al[tm], bh[tn]);
                }
        }
        __syncthreads();
    }
}

// ---------------- kernels ---------------------------------------------------
__global__ void __launch_bounds__(256) split_kernel(const float* __restrict__ x,
                                                    __nv_bfloat16* __restrict__ hi,
                                                    __nv_bfloat16* __restrict__ lo, int n4) {
    const int i = blockIdx.x * 256 + threadIdx.x;
    if (i >= n4) return;
    const float4 v = reinterpret_cast<const float4*>(x)[i];
    __nv_bfloat16 h[4], l[4];
    const float f[4] = {v.x, v.y, v.z, v.w};
#pragma unroll
    for (int j = 0; j < 4; ++j) {
        h[j] = __float2bfloat16(f[j]);
        l[j] = __float2bfloat16(f[j] - __bfloat162float(h[j]));
    }
    *reinterpret_cast<uint2*>(hi + (size_t)i * 4) = *reinterpret_cast<uint2*>(h);
    *reinterpret_cast<uint2*>(lo + (size_t)i * 4) = *reinterpret_cast<uint2*>(l);
}

__global__ void __launch_bounds__(256, 2) qkv_kernel() {
    __shared__ __align__(16) char sm[SM_TOTAL];
    const int z  = blockIdx.z;
    const int m0 = blockIdx.y * TM;
    const int n0 = blockIdx.x * TN;

    float acc[2][4][4];
#pragma unroll
    for (int a = 0; a < 2; ++a)
#pragma unroll
        for (int b = 0; b < 4; ++b)
#pragma unroll
            for (int cc = 0; cc < 4; ++cc) acc[a][b][cc] = 0.f;

    mma_mainloop(sm, g_Xhi + (size_t)m0 * D_, g_Xlo + (size_t)m0 * D_,
                 g_Whi[z] + (size_t)n0 * D_, g_Wlo[z] + (size_t)n0 * D_,
                 D_, D_, D_ / BK, false, acc);

    __nv_bfloat16* oh = (z == 0) ? g_Qhi : (z == 1) ? g_Khi : g_Vhi;
    __nv_bfloat16* ol = (z == 0) ? g_Qlo : (z == 1) ? g_Klo : g_Vlo;
    const int lane = threadIdx.x & 31, w = threadIdx.x >> 5;
    const int wm = w & 3, wn = w >> 2;
#pragma unroll
    for (int tm = 0; tm < 2; ++tm)
#pragma unroll
        for (int tn = 0; tn < 4; ++tn) {
            const int r = m0 + wm * 32 + tm * 16 + (lane >> 2);
            const int c = n0 + wn * 32 + tn * 8 + (lane & 3) * 2;
#pragma unroll
            for (int h = 0; h < 2; ++h) {
                const float f0 = acc[tm][tn][2 * h + 0], f1 = acc[tm][tn][2 * h + 1];
                const __nv_bfloat16 h0 = __float2bfloat16(f0), h1 = __float2bfloat16(f1);
                __nv_bfloat162 hp; hp.x = h0; hp.y = h1;
                __nv_bfloat162 lp;
                lp.x = __float2bfloat16(f0 - __bfloat162float(h0));
                lp.y = __float2bfloat16(f1 - __bfloat162float(h1));
                const size_t o = (size_t)(r + h * 8) * D_ + c;
                *reinterpret_cast<__nv_bfloat162*>(oh + o) = hp;
                *reinterpret_cast<__nv_bfloat162*>(ol + o) = lp;
            }
        }
}

__global__ void __launch_bounds__(256, 2) scores_kernel() {
    const int bx = blockIdx.x, by = blockIdx.y;
    if (bx * TN > by * TM + TM - 1) return;   // fully above diagonal
    __shared__ __align__(16) char sm[SM_TOTAL];
    const int b  = blockIdx.z;
    const int q0 = by * TM;
    const int k0 = bx * TN;

    float acc[2][4][4];
#pragma unroll
    for (int a = 0; a < 2; ++a)
#pragma unroll
        for (int bb = 0; bb < 4; ++bb)
#pragma unroll
            for (int cc = 0; cc < 4; ++cc) acc[a][bb][cc] = 0.f;

    const size_t qo = ((size_t)b * S_ + q0) * D_;
    const size_t ko = ((size_t)b * S_ + k0) * D_;
    mma_mainloop(sm, g_Qhi + qo, g_Qlo + qo, g_Khi + ko, g_Klo + ko,
                 D_, D_, D_ / BK, false, acc);

    const int lane = threadIdx.x & 31, w = threadIdx.x >> 5;
    const int wm = w & 3, wn = w >> 2;
#pragma unroll
    for (int tm = 0; tm < 2; ++tm)
#pragma unroll
        for (int tn = 0; tn < 4; ++tn) {
            const int r = q0 + wm * 32 + tm * 16 + (lane >> 2);
            const int c = k0 + wn * 32 + tn * 8 + (lane & 3) * 2;
#pragma unroll
            for (int h = 0; h < 2; ++h) {
                float2 v;
                v.x = acc[tm][tn][2 * h + 0] * 0.03125f;
                v.y = acc[tm][tn][2 * h + 1] * 0.03125f;
                *reinterpret_cast<float2*>(g_S + ((size_t)b * S_ + r + h * 8) * S_ + c) = v;
            }
        }
}

__global__ void __launch_bounds__(256) softmax_kernel() {
    const int q = blockIdx.x, b = blockIdx.y;
    const float* row = g_S + ((size_t)b * S_ + q) * S_;
    __nv_bfloat16* ph = g_Phi + ((size_t)b * S_ + q) * S_;
    __nv_bfloat16* pl = g_Plo + ((size_t)b * S_ + q) * S_;
    const int L = q + 1;
    const int tid = threadIdx.x;
    __shared__ float buf[S_];
    __shared__ float red[256];

    float m = -3.4e38f;
    for (int j = tid; j < L; j += 256) m = fmaxf(m, row[j]);
    red[tid] = m; __syncthreads();
    for (int s = 128; s > 0; s >>= 1) {
        if (tid < s) red[tid] = fmaxf(red[tid], red[tid + s]);
        __syncthreads();
    }
    m = red[0]; __syncthreads();

    float s = 0.f;
    for (int j = tid; j < L; j += 256) {
        const float e = expf(row[j] - m);
        buf[j] = e;
        s += e;
    }
    red[tid] = s; __syncthreads();
    for (int st = 128; st > 0; st >>= 1) {
        if (tid < st) red[tid] += red[tid + st];
        __syncthreads();
    }
    const float inv = 1.f / red[0];
    for (int j = tid; j < L; j += 256) {
        const float p = buf[j] * inv;
        const __nv_bfloat16 h = __float2bfloat16(p);
        ph[j] = h;
        pl[j] = __float2bfloat16(p - __bfloat162float(h));
    }
    const __nv_bfloat16 z = __float2bfloat16(0.f);
    for (int j = L + tid; j < S_; j += 256) { ph[j] = z; pl[j] = z; }
}

__global__ void __launch_bounds__(256, 2) pv_kernel(float* __restrict__ Out) {
    __shared__ __align__(16) char sm[SM_TOTAL];
    const int b  = blockIdx.z;
    const int q0 = blockIdx.y * TM;
    const int e0 = blockIdx.x * TN;
    const int nchunks = (q0 + TM) / BK;      // causal frontier

    float acc[2][4][4];
#pragma unroll
    for (int a = 0; a < 2; ++a)
#pragma unroll
        for (int bb = 0; bb < 4; ++bb)
#pragma unroll
            for (int cc = 0; cc < 4; ++cc) acc[a][bb][cc] = 0.f;

    const size_t po = ((size_t)b * S_ + q0) * S_;
    const size_t vo = (size_t)b * S_ * D_ + e0;
    mma_mainloop(sm, g_Phi + po, g_Plo + po, g_Vhi + vo, g_Vlo + vo,
                 S_, D_, nchunks, true, acc);

    const int lane = threadIdx.x & 31, w = threadIdx.x >> 5;
    const int wm = w & 3, wn = w >> 2;
#pragma unroll
    for (int tm = 0; tm < 2; ++tm)
#pragma unroll
        for (int tn = 0; tn < 4; ++tn) {
            const int r = q0 + wm * 32 + tm * 16 + (lane >> 2);
            const int c = e0 + wn * 32 + tn * 8 + (lane & 3) * 2;
#pragma unroll
            for (int h = 0; h < 2; ++h) {
                float2 v;
                v.x = acc[tm][tn][2 * h + 0];
                v.y = acc[tm][tn][2 * h + 1];
                *reinterpret_cast<float2*>(Out + ((size_t)b * S_ + r + h * 8) * D_ + c) = v;
            }
        }
}

// ---------------- launch ----------------------------------------------------
extern "C" void kernel_launch(void* const* d_in, const int* in_sizes, int n_in,
                              void* d_out, int out_size)
{
    (void)in_sizes; (void)n_in; (void)out_size;
    const float* X  = (const float*)d_in[0];
    const float* WQ = (const float*)d_in[1];
    const float* WK = (const float*)d_in[2];
    const float* WV = (const float*)d_in[3];
    float* out = (float*)d_out;

    __nv_bfloat16 *xhi, *xlo, *whi, *wlo;
    cudaGetSymbolAddress((void**)&xhi, g_Xhi);
    cudaGetSymbolAddress((void**)&xlo, g_Xlo);
    cudaGetSymbolAddress((void**)&whi, g_Whi);
    cudaGetSymbolAddress((void**)&wlo, g_Wlo);

    const int nX4 = (B_ * S_ * D_) / 4;
    const int nW4 = (D_ * D_) / 4;
    split_kernel<<<nX4 / 256, 256>>>(X,  xhi, xlo, nX4);
    split_kernel<<<nW4 / 256, 256>>>(WQ, whi + 0ull * D_ * D_, wlo + 0ull * D_ * D_, nW4);
    split_kernel<<<nW4 / 256, 256>>>(WK, whi + 1ull * D_ * D_, wlo + 1ull * D_ * D_, nW4);
    split_kernel<<<nW4 / 256, 256>>>(WV, whi + 2ull * D_ * D_, wlo + 2ull * D_ * D_, nW4);

    qkv_kernel    <<<dim3(D_ / TN, (B_ * S_) / TM, 3), 256>>>();
    scores_kernel <<<dim3(S_ / TN, S_ / TM, B_),       256>>>();
    softmax_kernel<<<dim3(S_, B_), 256>>>();
    pv_kernel     <<<dim3(D_ / TN, S_ / TM, B_),       256>>>(out);
}

// round 6
// speedup vs baseline: 2.1833x; 1.1447x over previous
#include <cuda_runtime.h>
#include <cuda_bf16.h>
#include <cstdint>
#include <math.h>

// Causal self-attention B=4,S=2048,D=1024 fp32.
// HMMA (mma.sync bf16) split-precision path + cp.async double-buffered staging.
// GEMM = Ahi*Bhi + Ahi*Blo + Alo*Bhi, fp32 accumulate (rel_err ~1.6e-5).

#define B_  4
#define S_  2048
#define D_  1024
#define TM  128
#define TN  64
#define BK  32

// per-stage smem layout (bytes)
#define A_STRIDE_B    80
#define B_NT_STRIDE_B 80
#define B_NN_STRIDE_B 144
#define OFF_AH 0
#define OFF_AL 10240
#define OFF_BH 20480
#define OFF_BL 26240
#define STAGE_BYTES 32000
#define SMEM_TOTAL  (2 * STAGE_BYTES)   // 64000 B dynamic smem

// ---------------- scratch --------------------------------------------------
__device__ alignas(256) __nv_bfloat16 g_Xhi[(size_t)B_*S_*D_], g_Xlo[(size_t)B_*S_*D_];
__device__ alignas(256) __nv_bfloat16 g_Whi[3][(size_t)D_*D_], g_Wlo[3][(size_t)D_*D_];
__device__ alignas(256) __nv_bfloat16 g_Qhi[(size_t)B_*S_*D_], g_Qlo[(size_t)B_*S_*D_];
__device__ alignas(256) __nv_bfloat16 g_Khi[(size_t)B_*S_*D_], g_Klo[(size_t)B_*S_*D_];
__device__ alignas(256) __nv_bfloat16 g_Vhi[(size_t)B_*S_*D_], g_Vlo[(size_t)B_*S_*D_];
__device__ alignas(256) float         g_S[(size_t)B_*S_*S_];
__device__ alignas(256) __nv_bfloat16 g_Phi[(size_t)B_*S_*S_], g_Plo[(size_t)B_*S_*S_];

// ---------------- PTX helpers ----------------------------------------------
__device__ __forceinline__ uint32_t smem_u32(const void* p) {
    uint32_t a;
    asm("{ .reg .u64 t; cvta.to.shared.u64 t, %1; cvt.u32.u64 %0, t; }" : "=r"(a) : "l"(p));
    return a;
}
__device__ __forceinline__ void cp16(uint32_t dst, const void* src) {
    asm volatile("cp.async.cg.shared.global [%0], [%1], 16;" :: "r"(dst), "l"(src));
}
__device__ __forceinline__ void cp_commit() {
    asm volatile("cp.async.commit_group;" ::: "memory");
}
template <int N>
__device__ __forceinline__ void cp_wait() {
    asm volatile("cp.async.wait_group %0;" :: "n"(N) : "memory");
}
__device__ __forceinline__ void ldm_x4(uint32_t* r, uint32_t addr) {
    asm volatile("ldmatrix.sync.aligned.m8n8.x4.shared.b16 {%0,%1,%2,%3}, [%4];"
                 : "=r"(r[0]), "=r"(r[1]), "=r"(r[2]), "=r"(r[3]) : "r"(addr));
}
__device__ __forceinline__ void ldm_x2(uint32_t* r, uint32_t addr) {
    asm volatile("ldmatrix.sync.aligned.m8n8.x2.shared.b16 {%0,%1}, [%2];"
                 : "=r"(r[0]), "=r"(r[1]) : "r"(addr));
}
__device__ __forceinline__ void ldm_x2_t(uint32_t* r, uint32_t addr) {
    asm volatile("ldmatrix.sync.aligned.m8n8.x2.trans.shared.b16 {%0,%1}, [%2];"
                 : "=r"(r[0]), "=r"(r[1]) : "r"(addr));
}
__device__ __forceinline__ void mma_bf16(float* d, const uint32_t* a, const uint32_t* b) {
    asm volatile("mma.sync.aligned.m16n8k16.row.col.f32.bf16.bf16.f32 "
                 "{%0,%1,%2,%3}, {%4,%5,%6,%7}, {%8,%9}, {%0,%1,%2,%3};"
                 : "+f"(d[0]), "+f"(d[1]), "+f"(d[2]), "+f"(d[3])
                 : "r"(a[0]), "r"(a[1]), "r"(a[2]), "r"(a[3]), "r"(b[0]), "r"(b[1]));
}

// ---------------- cp.async staging -----------------------------------------
__device__ __forceinline__ void stage_A_cp(uint32_t dst, const __nv_bfloat16* src,
                                           int ld, int k0) {
    const int tid = threadIdx.x;
#pragma unroll
    for (int i = 0; i < 2; ++i) {
        const int s = tid + i * 256;
        const int row = s >> 2, seg = s & 3;
        cp16(dst + row * A_STRIDE_B + seg * 16, src + (size_t)row * ld + k0 + seg * 8);
    }
}
__device__ __forceinline__ void stage_B_nt_cp(uint32_t dst, const __nv_bfloat16* src,
                                              int ld, int k0) {
    const int s = threadIdx.x;
    const int row = s >> 2, seg = s & 3;
    cp16(dst + row * B_NT_STRIDE_B + seg * 16, src + (size_t)row * ld + k0 + seg * 8);
}
__device__ __forceinline__ void stage_B_nn_cp(uint32_t dst, const __nv_bfloat16* src,
                                              int ld, int k0) {
    const int s = threadIdx.x;
    const int row = s >> 3, seg = s & 7;
    cp16(dst + row * B_NN_STRIDE_B + seg * 16, src + (size_t)(k0 + row) * ld + seg * 8);
}

// ---------------- 3-term pipelined mainloop ---------------------------------
__device__ __forceinline__ void mma_mainloop(
    uint32_t sb, const __nv_bfloat16* Ah, const __nv_bfloat16* Al,
    const __nv_bfloat16* Bh, const __nv_bfloat16* Bl,
    int lda, int ldb, int nchunks, bool nnB, float acc[2][4][4])
{
    const int tid = threadIdx.x;
    const int lane = tid & 31, w = tid >> 5;
    const int wm = w & 3, wn = w >> 2;

    const uint32_t a_off   = (uint32_t)(wm * 32 + (lane & 15)) * A_STRIDE_B + ((lane >> 4) << 3) * 2;
    const uint32_t bnt_off = (uint32_t)(wn * 32 + (lane & 7)) * B_NT_STRIDE_B + ((lane >> 3) & 1) * 16;
    const uint32_t bnn_off = (uint32_t)(lane & 15) * B_NN_STRIDE_B + (uint32_t)(wn * 32) * 2;

    auto issue = [&](int c) {
        const uint32_t buf = sb + (uint32_t)(c & 1) * STAGE_BYTES;
        const int k0 = c * BK;
        stage_A_cp(buf + OFF_AH, Ah, lda, k0);
        stage_A_cp(buf + OFF_AL, Al, lda, k0);
        if (nnB) { stage_B_nn_cp(buf + OFF_BH, Bh, ldb, k0);
                   stage_B_nn_cp(buf + OFF_BL, Bl, ldb, k0); }
        else     { stage_B_nt_cp(buf + OFF_BH, Bh, ldb, k0);
                   stage_B_nt_cp(buf + OFF_BL, Bl, ldb, k0); }
        cp_commit();
    };

    issue(0);
    for (int c = 0; c < nchunks; ++c) {
        if (c + 1 < nchunks) { issue(c + 1); cp_wait<1>(); }
        else                 { cp_wait<0>(); }
        __syncthreads();

        const uint32_t buf = sb + (uint32_t)(c & 1) * STAGE_BYTES;
#pragma unroll
        for (int ks = 0; ks < 2; ++ks) {
            const uint32_t kb = ks * 32;
            uint32_t ah[2][4], al[2][4], bh[4][2], bl[4][2];
#pragma unroll
            for (int tm = 0; tm < 2; ++tm) {
                ldm_x4(ah[tm], buf + OFF_AH + a_off + tm * (16 * A_STRIDE_B) + kb);
                ldm_x4(al[tm], buf + OFF_AL + a_off + tm * (16 * A_STRIDE_B) + kb);
            }
            if (nnB) {
#pragma unroll
                for (int tn = 0; tn < 4; ++tn) {
                    ldm_x2_t(bh[tn], buf + OFF_BH + bnn_off + kb * (B_NN_STRIDE_B / 2) + tn * 16);
                    ldm_x2_t(bl[tn], buf + OFF_BL + bnn_off + kb * (B_NN_STRIDE_B / 2) + tn * 16);
                }
            } else {
#pragma unroll
                for (int tn = 0; tn < 4; ++tn) {
                    ldm_x2(bh[tn], buf + OFF_BH + bnt_off + tn * (8 * B_NT_STRIDE_B) + kb);
                    ldm_x2(bl[tn], buf + OFF_BL + bnt_off + tn * (8 * B_NT_STRIDE_B) + kb);
                }
            }
#pragma unroll
            for (int tm = 0; tm < 2; ++tm)
#pragma unroll
                for (int tn = 0; tn < 4; ++tn) {
                    mma_bf16(acc[tm][tn], ah[tm], bh[tn]);
                    mma_bf16(acc[tm][tn], ah[tm], bl[tn]);
                    mma_bf16(acc[tm][tn], al[tm], bh[tn]);
                }
        }
        __syncthreads();
    }
}

// ---------------- kernels ---------------------------------------------------
__global__ void __launch_bounds__(256) split_kernel(
    const float* __restrict__ X, const float* __restrict__ WQ,
    const float* __restrict__ WK, const float* __restrict__ WV)
{
    const int nX4 = (B_ * S_ * D_) / 4;
    const int nW4 = (D_ * D_) / 4;
    const int i = blockIdx.x * 256 + threadIdx.x;

    const float* src; __nv_bfloat16 *hi, *lo; int idx;
    if (i < nX4)                { src = X;  hi = g_Xhi;    lo = g_Xlo;    idx = i; }
    else if (i < nX4 + nW4)     { src = WQ; hi = g_Whi[0]; lo = g_Wlo[0]; idx = i - nX4; }
    else if (i < nX4 + 2 * nW4) { src = WK; hi = g_Whi[1]; lo = g_Wlo[1]; idx = i - nX4 - nW4; }
    else                        { src = WV; hi = g_Whi[2]; lo = g_Wlo[2]; idx = i - nX4 - 2 * nW4; }

    const float4 v = reinterpret_cast<const float4*>(src)[idx];
    __nv_bfloat16 h[4], l[4];
    const float f[4] = {v.x, v.y, v.z, v.w};
#pragma unroll
    for (int j = 0; j < 4; ++j) {
        h[j] = __float2bfloat16(f[j]);
        l[j] = __float2bfloat16(f[j] - __bfloat162float(h[j]));
    }
    *reinterpret_cast<uint2*>(hi + (size_t)idx * 4) = *reinterpret_cast<uint2*>(h);
    *reinterpret_cast<uint2*>(lo + (size_t)idx * 4) = *reinterpret_cast<uint2*>(l);
}

__global__ void __launch_bounds__(256, 2) qkv_kernel() {
    extern __shared__ __align__(16) char smdyn[];
    const uint32_t sb = smem_u32(smdyn);
    const int z  = blockIdx.z;
    const int m0 = blockIdx.y * TM;
    const int n0 = blockIdx.x * TN;

    float acc[2][4][4];
#pragma unroll
    for (int a = 0; a < 2; ++a)
#pragma unroll
        for (int b = 0; b < 4; ++b)
#pragma unroll
            for (int cc = 0; cc < 4; ++cc) acc[a][b][cc] = 0.f;

    mma_mainloop(sb, g_Xhi + (size_t)m0 * D_, g_Xlo + (size_t)m0 * D_,
                 g_Whi[z] + (size_t)n0 * D_, g_Wlo[z] + (size_t)n0 * D_,
                 D_, D_, D_ / BK, false, acc);

    __nv_bfloat16* oh = (z == 0) ? g_Qhi : (z == 1) ? g_Khi : g_Vhi;
    __nv_bfloat16* ol = (z == 0) ? g_Qlo : (z == 1) ? g_Klo : g_Vlo;
    const int lane = threadIdx.x & 31, w = threadIdx.x >> 5;
    const int wm = w & 3, wn = w >> 2;
#pragma unroll
    for (int tm = 0; tm < 2; ++tm)
#pragma unroll
        for (int tn = 0; tn < 4; ++tn) {
            const int r = m0 + wm * 32 + tm * 16 + (lane >> 2);
            const int c = n0 + wn * 32 + tn * 8 + (lane & 3) * 2;
#pragma unroll
            for (int h = 0; h < 2; ++h) {
                const float f0 = acc[tm][tn][2 * h + 0], f1 = acc[tm][tn][2 * h + 1];
                const __nv_bfloat16 h0 = __float2bfloat16(f0), h1 = __float2bfloat16(f1);
                __nv_bfloat162 hp; hp.x = h0; hp.y = h1;
                __nv_bfloat162 lp;
                lp.x = __float2bfloat16(f0 - __bfloat162float(h0));
                lp.y = __float2bfloat16(f1 - __bfloat162float(h1));
                const size_t o = (size_t)(r + h * 8) * D_ + c;
                *reinterpret_cast<__nv_bfloat162*>(oh + o) = hp;
                *reinterpret_cast<__nv_bfloat162*>(ol + o) = lp;
            }
        }
}

__global__ void __launch_bounds__(256, 2) scores_kernel() {
    const int bx = blockIdx.x, by = blockIdx.y;
    if (bx * TN > by * TM + TM - 1) return;
    extern __shared__ __align__(16) char smdyn[];
    const uint32_t sb = smem_u32(smdyn);
    const int b  = blockIdx.z;
    const int q0 = by * TM;
    const int k0 = bx * TN;

    float acc[2][4][4];
#pragma unroll
    for (int a = 0; a < 2; ++a)
#pragma unroll
        for (int bb = 0; bb < 4; ++bb)
#pragma unroll
            for (int cc = 0; cc < 4; ++cc) acc[a][bb][cc] = 0.f;

    const size_t qo = ((size_t)b * S_ + q0) * D_;
    const size_t ko = ((size_t)b * S_ + k0) * D_;
    mma_mainloop(sb, g_Qhi + qo, g_Qlo + qo, g_Khi + ko, g_Klo + ko,
                 D_, D_, D_ / BK, false, acc);

    const int lane = threadIdx.x & 31, w = threadIdx.x >> 5;
    const int wm = w & 3, wn = w >> 2;
#pragma unroll
    for (int tm = 0; tm < 2; ++tm)
#pragma unroll
        for (int tn = 0; tn < 4; ++tn) {
            const int r = q0 + wm * 32 + tm * 16 + (lane >> 2);
            const int c = k0 + wn * 32 + tn * 8 + (lane & 3) * 2;
#pragma unroll
            for (int h = 0; h < 2; ++h) {
                float2 v;
                v.x = acc[tm][tn][2 * h + 0] * 0.03125f;
                v.y = acc[tm][tn][2 * h + 1] * 0.03125f;
                *reinterpret_cast<float2*>(g_S + ((size_t)b * S_ + r + h * 8) * S_ + c) = v;
            }
        }
}

__global__ void __launch_bounds__(256) softmax_kernel() {
    const int q = blockIdx.x, b = blockIdx.y;
    const float* row = g_S + ((size_t)b * S_ + q) * S_;
    __nv_bfloat16* ph = g_Phi + ((size_t)b * S_ + q) * S_;
    __nv_bfloat16* pl = g_Plo + ((size_t)b * S_ + q) * S_;
    const int L = q + 1;
    const int tid = threadIdx.x;
    __shared__ float buf[S_];
    __shared__ float red[256];

    float m = -3.4e38f;
    for (int j = tid; j < L; j += 256) m = fmaxf(m, row[j]);
    red[tid] = m; __syncthreads();
    for (int s = 128; s > 0; s >>= 1) {
        if (tid < s) red[tid] = fmaxf(red[tid], red[tid + s]);
        __syncthreads();
    }
    m = red[0]; __syncthreads();

    float s = 0.f;
    for (int j = tid; j < L; j += 256) {
        const float e = expf(row[j] - m);
        buf[j] = e;
        s += e;
    }
    red[tid] = s; __syncthreads();
    for (int st = 128; st > 0; st >>= 1) {
        if (tid < st) red[tid] += red[tid + st];
        __syncthreads();
    }
    const float inv = 1.f / red[0];
    for (int j = tid; j < L; j += 256) {
        const float p = buf[j] * inv;
        const __nv_bfloat16 h = __float2bfloat16(p);
        ph[j] = h;
        pl[j] = __float2bfloat16(p - __bfloat162float(h));
    }
    const __nv_bfloat16 z = __float2bfloat16(0.f);
    for (int j = L + tid; j < S_; j += 256) { ph[j] = z; pl[j] = z; }
}

__global__ void __launch_bounds__(256, 2) pv_kernel(float* __restrict__ Out) {
    extern __shared__ __align__(16) char smdyn[];
    const uint32_t sb = smem_u32(smdyn);
    const int b  = blockIdx.z;
    const int q0 = blockIdx.y * TM;
    const int e0 = blockIdx.x * TN;
    const int nchunks = (q0 + TM) / BK;

    float acc[2][4][4];
#pragma unroll
    for (int a = 0; a < 2; ++a)
#pragma unroll
        for (int bb = 0; bb < 4; ++bb)
#pragma unroll
            for (int cc = 0; cc < 4; ++cc) acc[a][bb][cc] = 0.f;

    const size_t po = ((size_t)b * S_ + q0) * S_;
    const size_t vo = (size_t)b * S_ * D_ + e0;
    mma_mainloop(sb, g_Phi + po, g_Plo + po, g_Vhi + vo, g_Vlo + vo,
                 S_, D_, nchunks, true, acc);

    const int lane = threadIdx.x & 31, w = threadIdx.x >> 5;
    const int wm = w & 3, wn = w >> 2;
#pragma unroll
    for (int tm = 0; tm < 2; ++tm)
#pragma unroll
        for (int tn = 0; tn < 4; ++tn) {
            const int r = q0 + wm * 32 + tm * 16 + (lane >> 2);
            const int c = e0 + wn * 32 + tn * 8 + (lane & 3) * 2;
#pragma unroll
            for (int h = 0; h < 2; ++h) {
                float2 v;
                v.x = acc[tm][tn][2 * h + 0];
                v.y = acc[tm][tn][2 * h + 1];
                *reinterpret_cast<float2*>(Out + ((size_t)b * S_ + r + h * 8) * D_ + c) = v;
            }
        }
}

// ---------------- launch ----------------------------------------------------
extern "C" void kernel_launch(void* const* d_in, const int* in_sizes, int n_in,
                              void* d_out, int out_size)
{
    (void)in_sizes; (void)n_in; (void)out_size;
    const float* X  = (const float*)d_in[0];
    const float* WQ = (const float*)d_in[1];
    const float* WK = (const float*)d_in[2];
    const float* WV = (const float*)d_in[3];
    float* out = (float*)d_out;

    // Unconditional (no static state): idempotent, not stream-ordered, capture-safe.
    cudaFuncSetAttribute(qkv_kernel,    cudaFuncAttributeMaxDynamicSharedMemorySize, SMEM_TOTAL);
    cudaFuncSetAttribute(scores_kernel, cudaFuncAttributeMaxDynamicSharedMemorySize, SMEM_TOTAL);
    cudaFuncSetAttribute(pv_kernel,     cudaFuncAttributeMaxDynamicSharedMemorySize, SMEM_TOTAL);

    const int ntot4 = (B_ * S_ * D_ + 3 * D_ * D_) / 4;
    split_kernel<<<(ntot4 + 255) / 256, 256>>>(X, WQ, WK, WV);

    qkv_kernel    <<<dim3(D_ / TN, (B_ * S_) / TM, 3), 256, SMEM_TOTAL>>>();
    scores_kernel <<<dim3(S_ / TN, S_ / TM, B_),       256, SMEM_TOTAL>>>();
    softmax_kernel<<<dim3(S_, B_), 256>>>();
    pv_kernel     <<<dim3(D_ / TN, S_ / TM, B_),       256, SMEM_TOTAL>>>(out);
}